// round 10
// baseline (speedup 1.0000x reference)
#include <cuda_runtime.h>
#include <cstdint>
#include <cstdio>

// Problem constants (fixed by the dataset)
#define C_DIM 22
#define T_DIM 4000
#define M_DIM 16
#define B_DIM 16

// Kernel tiling
#define TT      1024      // t-tile per stage buffer
#define NTILES  4         // ceil(4000/1024)
#define BLOCK   256

typedef unsigned long long u64;

// packed dual-fp32 FMA: d = a*b + c (elementwise on {lo,hi})
__device__ __forceinline__ u64 fma2(u64 a, u64 b, u64 c) {
    u64 d;
    asm("fma.rn.f32x2 %0, %1, %2, %3;" : "=l"(d) : "l"(a), "l"(b), "l"(c));
    return d;
}
__device__ __forceinline__ u64 pack2(float lo, float hi) {
    u64 d; asm("mov.b64 %0, {%1, %2};" : "=l"(d) : "f"(lo), "f"(hi)); return d;
}
__device__ __forceinline__ u64 dup2(float v) {
    u64 d; asm("mov.b64 %0, {%1, %1};" : "=l"(d) : "f"(v)); return d;
}

// One block per (n,b) pair. Computes out[n,b,m] = log(diag[m] / sum_m diag[m]),
// diag[m] = sum_t (sum_c W[b,m,c] * x[n,b,c,t])^2  (the 1/sqrt(T) scale cancels
// in the ratio, so it is skipped).
__global__ void __launch_bounds__(BLOCK, 1)
csp_kernel(const float* __restrict__ xfb, const float* __restrict__ WT,
           float* __restrict__ out)
{
    extern __shared__ float sm[];
    float* xbuf0 = sm;                      // 22*1024 floats
    float* xbuf1 = sm + C_DIM * TT;         // 22*1024 floats
    float* wraw  = sm + 2 * C_DIM * TT;     // 352 floats
    float* red   = wraw + (M_DIM * C_DIM);  // 32 floats scratch

    const int bx   = blockIdx.x;            // n*16 + b
    const int b    = bx & (B_DIM - 1);
    const float* gx = xfb + (size_t)bx * (C_DIM * T_DIM);
    const int tid  = threadIdx.x;
    const int lane = tid & 31;
    const int wid  = tid >> 5;
    const int g    = wid & 3;                // m-group: m in [4g, 4g+4)
    const int h    = wid >> 2;               // t-half within tile

    // Stage raw W[b] (352 floats) into smem
    if (tid < (M_DIM * C_DIM) / 2) {
        ((float2*)wraw)[tid] = ((const float2*)(WT + b * (M_DIM * C_DIM)))[tid];
    }

    // Prefetch tile 0 (fully in-bounds: t in [0,1024))
    {
        const int t4 = tid << 2;
        #pragma unroll
        for (int c = 0; c < C_DIM; c++) {
            unsigned sa = (unsigned)__cvta_generic_to_shared(xbuf0 + c * TT + t4);
            asm volatile("cp.async.cg.shared.global [%0], [%1], 16;"
                         :: "r"(sa), "l"(gx + c * T_DIM + t4));
        }
    }
    asm volatile("cp.async.commit_group;");

    __syncthreads();   // wraw visible

    // Pack this warp's 4 rows of W into registers as m-pairs:
    // w0[c] = {W[4g+0][c], W[4g+1][c]},  w1[c] = {W[4g+2][c], W[4g+3][c]}
    u64 w0[C_DIM], w1[C_DIM];
    {
        const float* wg = wraw + (g * 4) * C_DIM;
        #pragma unroll
        for (int c = 0; c < C_DIM; c++) {
            w0[c] = pack2(wg[c],             wg[C_DIM + c]);
            w1[c] = pack2(wg[2 * C_DIM + c], wg[3 * C_DIM + c]);
        }
    }

    u64 acc0 = 0ull, acc1 = 0ull;           // {sum z^2} packed over m-pairs
    const int tlb = (h << 9) + lane;         // this warp's base t within a tile

    for (int k = 0; k < NTILES; k++) {
        // Prefetch tile k+1 into the other buffer (safe: that buffer was last
        // read in iteration k-1 which ended with a __syncthreads()).
        if (k < NTILES - 1) {
            float* dst = ((k + 1) & 1) ? xbuf1 : xbuf0;
            const int tg = (k + 1) * TT + (tid << 2);
            const unsigned ss = (tg < T_DIM) ? 16u : 0u;     // zero-fill tail
            const float* srcb = ss ? (gx + tg) : gx;          // clamp OOB addr
            #pragma unroll
            for (int c = 0; c < C_DIM; c++) {
                unsigned sa = (unsigned)__cvta_generic_to_shared(dst + c * TT + (tid << 2));
                asm volatile("cp.async.cg.shared.global [%0], [%1], 16, %2;"
                             :: "r"(sa), "l"(srcb + c * T_DIM), "r"(ss));
            }
        }
        asm volatile("cp.async.commit_group;");
        asm volatile("cp.async.wait_group 1;");   // tile k complete
        __syncthreads();

        const float* xs = (k & 1) ? xbuf1 : xbuf0;

        #pragma unroll 2
        for (int it = 0; it < 16; it++) {
            const float* xp = xs + tlb + (it << 5);
            u64 z0 = 0ull, z1 = 0ull;
            #pragma unroll
            for (int c = 0; c < C_DIM; c++) {
                u64 xd = dup2(xp[c * TT]);
                z0 = fma2(w0[c], xd, z0);
                z1 = fma2(w1[c], xd, z1);
            }
            acc0 = fma2(z0, z0, acc0);
            acc1 = fma2(z1, z1, acc1);
        }
        __syncthreads();   // everyone done reading xs before it is re-staged
    }

    // ---- reduction: diag[m] over lanes, then over the two t-half warps ----
    float a0, a1, a2, a3;
    asm("mov.b64 {%0, %1}, %2;" : "=f"(a0), "=f"(a1) : "l"(acc0));
    asm("mov.b64 {%0, %1}, %2;" : "=f"(a2), "=f"(a3) : "l"(acc1));
    #pragma unroll
    for (int off = 16; off; off >>= 1) {
        a0 += __shfl_xor_sync(0xffffffffu, a0, off);
        a1 += __shfl_xor_sync(0xffffffffu, a1, off);
        a2 += __shfl_xor_sync(0xffffffffu, a2, off);
        a3 += __shfl_xor_sync(0xffffffffu, a3, off);
    }
    if (lane == 0) {
        red[wid * 4 + 0] = a0;  red[wid * 4 + 1] = a1;
        red[wid * 4 + 2] = a2;  red[wid * 4 + 3] = a3;
    }
    __syncthreads();

    // red[m] (h=0 warps) + red[16+m] (h=1 warps) -> diag[m]
    if (tid < M_DIM) {
        red[tid] = red[tid] + red[M_DIM + tid];
    }
    __syncthreads();

    if (tid < M_DIM) {
        float tot = 0.f;
        #pragma unroll
        for (int j = 0; j < M_DIM; j++) tot += red[j];
        out[bx * M_DIM + tid] = logf(red[tid] / tot);
    }
}

extern "C" void kernel_launch(void* const* d_in, const int* in_sizes, int n_in,
                              void* d_out, int out_size) {
    const float* xfb = (const float*)d_in[0];
    const float* WT  = (const float*)d_in[1];
    int nx = in_sizes[0];
    // Defensive: ensure xfb is the big tensor
    if (n_in >= 2 && in_sizes[0] < in_sizes[1]) {
        xfb = (const float*)d_in[1];
        WT  = (const float*)d_in[0];
        nx  = in_sizes[1];
    }
    const int nb = nx / (C_DIM * T_DIM);     // = 1024 blocks (N*B)

    const size_t smem_bytes =
        (size_t)(2 * C_DIM * TT + M_DIM * C_DIM + 64) * sizeof(float);

    cudaFuncSetAttribute((const void*)csp_kernel,
                         cudaFuncAttributeMaxDynamicSharedMemorySize,
                         (int)smem_bytes);

    csp_kernel<<<nb, BLOCK, smem_bytes>>>(xfb, WT, (float*)d_out);
}

// round 11
// speedup vs baseline: 1.1897x; 1.1897x over previous
#include <cuda_runtime.h>
#include <cstdint>

// Problem constants (fixed by the dataset)
#define C_DIM 22
#define T_DIM 4000
#define M_DIM 16
#define B_DIM 16

// Tiling
#define TT      1024      // t-tile per stage buffer
#define NTILES  4         // ceil(4000/1024)
#define BLOCK   256
#define GRID_P  148       // persistent CTAs (~1/SM)

typedef unsigned long long u64;

// packed dual-fp32 FMA: d = a*b + c (elementwise on {lo,hi})
__device__ __forceinline__ u64 fma2(u64 a, u64 b, u64 c) {
    u64 d;
    asm("fma.rn.f32x2 %0, %1, %2, %3;" : "=l"(d) : "l"(a), "l"(b), "l"(c));
    return d;
}
__device__ __forceinline__ u64 dup2(float v) {
    u64 d; asm("mov.b64 %0, {%1, %1};" : "=l"(d) : "f"(v)); return d;
}

// Stage one (item, tile) x-slab into smem: 22 rows x 1024 floats.
// Each thread copies 16B per row via cp.async; zero-fills the t>=4000 tail.
__device__ __forceinline__ void stage_tile(float* dst, const float* gx_item,
                                           int ktile, int tid)
{
    const int tg = ktile * TT + (tid << 2);          // global t of this thread's 16B
    const unsigned ss = (tg < T_DIM) ? 16u : 0u;     // zero-fill OOB tail
    const float* src = ss ? (gx_item + tg) : gx_item; // clamp OOB address
    const int soff = tid << 2;
    #pragma unroll
    for (int c = 0; c < C_DIM; c++) {
        unsigned sa = (unsigned)__cvta_generic_to_shared(dst + c * TT + soff);
        asm volatile("cp.async.cg.shared.global [%0], [%1], 16, %2;"
                     :: "r"(sa), "l"(src + c * T_DIM), "r"(ss));
    }
}

// Persistent kernel: each CTA processes items (n*16+b) with stride gridDim.x.
// out[item,m] = log(diag[m]/sum(diag)), diag[m] = sum_t (sum_c W[b,m,c]*x[c,t])^2.
// (The reference's 1/sqrt(T) scaling cancels in the ratio and is skipped.)
__global__ void __launch_bounds__(BLOCK, 1)
csp_kernel(const float* __restrict__ xfb, const float* __restrict__ WT,
           float* __restrict__ out, int n_items)
{
    extern __shared__ float sm[];
    float* xb0  = sm;                          // 22*1024 floats
    float* xb1  = sm + C_DIM * TT;             // 22*1024 floats
    float* wtab = sm + 2 * C_DIM * TT;         // 16*16*22 = 5632 floats (all b)
    float* red  = wtab + B_DIM * M_DIM * C_DIM;// 32 floats scratch

    const int tid  = threadIdx.x;
    const int lane = tid & 31;
    const int wid  = tid >> 5;
    const int g    = wid & 3;                  // m-group: m in [4g, 4g+4)
    const int h    = wid >> 2;                 // t-half within a tile

    int item = blockIdx.x;
    if (item >= n_items) return;

    const int stride = gridDim.x;

    // Kick off DRAM immediately: prefetch tile 0 of the first item.
    stage_tile(xb0, xfb + (size_t)item * (C_DIM * T_DIM), 0, tid);
    asm volatile("cp.async.commit_group;");

    // Stage the full WT table once (16 b's, 5632 floats).
    #pragma unroll
    for (int i = tid; i < (B_DIM * M_DIM * C_DIM) / 2; i += BLOCK)
        ((float2*)wtab)[i] = ((const float2*)WT)[i];
    __syncthreads();   // wtab visible before W register loads

    int pb = 0;        // parity: buffer holding the next tile to compute

    for (; item < n_items; item += stride) {
        const float* gx = xfb + (size_t)item * (C_DIM * T_DIM);
        const int nitem = item + stride;

        // This warp's 4 W rows, each value duplicated into an f32x2 pair.
        u64 w0[C_DIM], w1[C_DIM], w2[C_DIM], w3[C_DIM];
        {
            const float* wg = wtab + ((item & (B_DIM - 1)) * M_DIM + g * 4) * C_DIM;
            #pragma unroll
            for (int c = 0; c < C_DIM; c++) {
                w0[c] = dup2(wg[c]);
                w1[c] = dup2(wg[C_DIM + c]);
                w2[c] = dup2(wg[2 * C_DIM + c]);
                w3[c] = dup2(wg[3 * C_DIM + c]);
            }
        }

        u64 acc0 = 0ull, acc1 = 0ull, acc2 = 0ull, acc3 = 0ull;
        const int tlb = (h << 9) + (lane << 1);    // this thread's base t in a tile

        for (int k = 0; k < NTILES; k++) {
            // Prefetch the next tile (possibly tile 0 of the next item) into
            // the other buffer. Safe: that buffer was last read in the
            // previous iteration, which ended with __syncthreads().
            if (k < NTILES - 1) {
                stage_tile(pb ? xb0 : xb1, gx, k + 1, tid);
            } else if (nitem < n_items) {
                stage_tile(pb ? xb0 : xb1,
                           xfb + (size_t)nitem * (C_DIM * T_DIM), 0, tid);
            }
            asm volatile("cp.async.commit_group;");
            asm volatile("cp.async.wait_group 1;");   // current tile complete
            __syncthreads();

            const float* xs = pb ? xb1 : xb0;

            #pragma unroll 2
            for (int it = 0; it < 8; it++) {
                const float* xp = xs + tlb + (it << 6);
                u64 z0 = 0ull, z1 = 0ull, z2 = 0ull, z3 = 0ull;
                #pragma unroll
                for (int c = 0; c < C_DIM; c++) {
                    u64 xd = *(const u64*)(xp + c * TT);  // float2 of {t, t+1}
                    z0 = fma2(w0[c], xd, z0);
                    z1 = fma2(w1[c], xd, z1);
                    z2 = fma2(w2[c], xd, z2);
                    z3 = fma2(w3[c], xd, z3);
                }
                acc0 = fma2(z0, z0, acc0);
                acc1 = fma2(z1, z1, acc1);
                acc2 = fma2(z2, z2, acc2);
                acc3 = fma2(z3, z3, acc3);
            }
            __syncthreads();   // all reads of xs done before it is re-staged
            pb ^= 1;
        }

        // ---- per-item reduction: diag[m], then log-normalize ----
        float a0, a1, a2, a3;
        {
            float lo, hi;
            asm("mov.b64 {%0, %1}, %2;" : "=f"(lo), "=f"(hi) : "l"(acc0)); a0 = lo + hi;
            asm("mov.b64 {%0, %1}, %2;" : "=f"(lo), "=f"(hi) : "l"(acc1)); a1 = lo + hi;
            asm("mov.b64 {%0, %1}, %2;" : "=f"(lo), "=f"(hi) : "l"(acc2)); a2 = lo + hi;
            asm("mov.b64 {%0, %1}, %2;" : "=f"(lo), "=f"(hi) : "l"(acc3)); a3 = lo + hi;
        }
        #pragma unroll
        for (int off = 16; off; off >>= 1) {
            a0 += __shfl_xor_sync(0xffffffffu, a0, off);
            a1 += __shfl_xor_sync(0xffffffffu, a1, off);
            a2 += __shfl_xor_sync(0xffffffffu, a2, off);
            a3 += __shfl_xor_sync(0xffffffffu, a3, off);
        }
        if (lane == 0) {
            red[(h << 4) + g * 4 + 0] = a0;
            red[(h << 4) + g * 4 + 1] = a1;
            red[(h << 4) + g * 4 + 2] = a2;
            red[(h << 4) + g * 4 + 3] = a3;
        }
        __syncthreads();
        if (tid < M_DIM) red[tid] = red[tid] + red[M_DIM + tid];
        __syncthreads();
        if (tid < M_DIM) {
            float tot = 0.f;
            #pragma unroll
            for (int j = 0; j < M_DIM; j++) tot += red[j];
            out[item * M_DIM + tid] = logf(red[tid] / tot);
        }
        // No extra sync needed: the next item's first-tile wait+sync orders
        // everything, and red[] is not rewritten until after 4 more tiles.
    }
}

extern "C" void kernel_launch(void* const* d_in, const int* in_sizes, int n_in,
                              void* d_out, int out_size) {
    const float* xfb = (const float*)d_in[0];
    const float* WT  = (const float*)d_in[1];
    int nx = in_sizes[0];
    // Defensive: ensure xfb is the big tensor
    if (n_in >= 2 && in_sizes[0] < in_sizes[1]) {
        xfb = (const float*)d_in[1];
        WT  = (const float*)d_in[0];
        nx  = in_sizes[1];
    }
    const int n_items = nx / (C_DIM * T_DIM);   // = 1024 (N*B)

    const size_t smem_bytes =
        (size_t)(2 * C_DIM * TT + B_DIM * M_DIM * C_DIM + 64) * sizeof(float);

    cudaFuncSetAttribute((const void*)csp_kernel,
                         cudaFuncAttributeMaxDynamicSharedMemorySize,
                         (int)smem_bytes);

    const int grid = (n_items < GRID_P) ? n_items : GRID_P;
    csp_kernel<<<grid, BLOCK, smem_bytes>>>(xfb, WT, (float*)d_out, n_items);
}